// round 5
// baseline (speedup 1.0000x reference)
#include <cuda_runtime.h>
#include <cuda_bf16.h>

// Problem constants: H=32, T=8192, D=128
#define RP_H 32
#define RP_T 8192
#define RP_D 128
#define RP_ROWS (RP_H * RP_T)          // 262144
#define RP_HPW 4                       // heads per warp (cos/sin register reuse)
#define RP_HG (RP_H / RP_HPW)          // 8 head groups
#define RP_THREADS 256                 // 8 warps/block
#define RP_TPB 8                       // t-values per block (1 per warp)
#define RP_TBLOCKS (RP_T / RP_TPB)     // 1024
#define RP_BLOCKS (RP_HG * RP_TBLOCKS) // 8192

// Warp layout: one warp = one t, RP_HPW heads. cos/sin loaded ONCE per warp and
// reused for 4 x-rows -> 4x less L2 table traffic (LTS was the binding resource).
// Warps in a block take consecutive t -> each block touches 4KB-contiguous
// chunks of x/out per head (dense streams preserved).
__global__ __launch_bounds__(RP_THREADS, 6) void rope_minmax_kernel(
    const float* __restrict__ x,
    const float* __restrict__ cosb,
    const float* __restrict__ sinb,
    float* __restrict__ out,
    float* __restrict__ obs_max,
    float* __restrict__ obs_min)
{
    const unsigned FULL = 0xffffffffu;
    int wid  = threadIdx.x >> 5;
    int lane = threadIdx.x & 31;
    int hg   = blockIdx.x >> 10;                 // head group 0..7  (1024 t-blocks/group)
    int tb   = blockIdx.x & (RP_TBLOCKS - 1);    // t-block within group
    int t    = tb * RP_TPB + wid;                // this warp's t
    int h0   = hg * RP_HPW;                      // first head

    // ---- DRAM-bound x loads first: 4 independent LDG.128 (4 heads, same t) ----
    float4 v[RP_HPW];
    #pragma unroll
    for (int j = 0; j < RP_HPW; j++) {
        size_t row = (size_t)(h0 + j) * RP_T + t;
        v[j] = reinterpret_cast<const float4*>(x + row * RP_D)[lane];
    }

    // ---- table loads once, reused for all 4 heads ----
    float4 c = reinterpret_cast<const float4*>(cosb + (size_t)t * RP_D)[lane];
    float4 s = reinterpret_cast<const float4*>(sinb + (size_t)t * RP_D)[lane];

    float sign = (lane < 16) ? -1.0f : 1.0f;
    float4 sgs = make_float4(sign * s.x, sign * s.y, sign * s.z, sign * s.w);
    float mx[RP_HPW], mn[RP_HPW];

    #pragma unroll
    for (int j = 0; j < RP_HPW; j++) {
        // partner half (elements i +/- 64) lives in lane ^ 16
        float4 p;
        p.x = __shfl_xor_sync(FULL, v[j].x, 16);
        p.y = __shfl_xor_sync(FULL, v[j].y, 16);
        p.z = __shfl_xor_sync(FULL, v[j].z, 16);
        p.w = __shfl_xor_sync(FULL, v[j].w, 16);

        float4 o;
        o.x = fmaf(p.x, sgs.x, v[j].x * c.x);
        o.y = fmaf(p.y, sgs.y, v[j].y * c.y);
        o.z = fmaf(p.z, sgs.z, v[j].z * c.z);
        o.w = fmaf(p.w, sgs.w, v[j].w * c.w);

        size_t row = (size_t)(h0 + j) * RP_T + t;
        reinterpret_cast<float4*>(out + row * RP_D)[lane] = o;

        mx[j] = fmaxf(fmaxf(o.x, o.y), fmaxf(o.z, o.w));
        mn[j] = fminf(fminf(o.x, o.y), fminf(o.z, o.w));
    }

    // ---- 4 interleaved butterfly reductions ----
    #pragma unroll
    for (int off = 16; off > 0; off >>= 1) {
        #pragma unroll
        for (int j = 0; j < RP_HPW; j++) {
            mx[j] = fmaxf(mx[j], __shfl_xor_sync(FULL, mx[j], off));
            mn[j] = fminf(mn[j], __shfl_xor_sync(FULL, mn[j], off));
        }
    }

    // After butterfly every lane holds the result: lanes 0..3 each store one row's stats.
    if (lane < RP_HPW) {
        size_t row = (size_t)(h0 + lane) * RP_T + t;
        obs_max[row] = mx[lane];
        obs_min[row] = mn[lane];
    }
}

extern "C" void kernel_launch(void* const* d_in, const int* in_sizes, int n_in,
                              void* d_out, int out_size) {
    // Input order: x, scale_x (unused), cos, scale_cos (unused), sin, scale_sin (unused)
    const float* x    = (const float*)d_in[0];
    const float* cosb = (const float*)d_in[2];
    const float* sinb = (const float*)d_in[4];

    float* out     = (float*)d_out;                    // H*T*D
    float* obs_max = out + (size_t)RP_ROWS * RP_D;     // H*T
    float* obs_min = obs_max + (size_t)RP_ROWS;        // H*T

    rope_minmax_kernel<<<RP_BLOCKS, RP_THREADS>>>(x, cosb, sinb, out, obs_max, obs_min);
}

// round 6
// speedup vs baseline: 1.0106x; 1.0106x over previous
#include <cuda_runtime.h>
#include <cuda_bf16.h>

// Problem constants: H=32, T=8192, D=128
#define RP_H 32
#define RP_T 8192
#define RP_D 128
#define RP_ROWS (RP_H * RP_T)          // 262144
#define RP_HPW 4                       // heads per warp (cos/sin register reuse)
#define RP_HG (RP_H / RP_HPW)          // 8 head groups
#define RP_THREADS 256                 // 8 warps/block
#define RP_TPB 8                       // t-values per block (1 per warp)
#define RP_TBLOCKS (RP_T / RP_TPB)     // 1024
#define RP_BLOCKS (RP_HG * RP_TBLOCKS) // 8192

// R5 structure (one warp = one t, 4 heads; tables loaded once per warp) plus
// streaming cache hints: x = read-once (__ldcs), out = write-once (__stcs).
// Goal: smooth steady-state writeback so back-to-back graph replays don't
// burst dirty-L2 evictions into the next replay's read stream.
__global__ __launch_bounds__(RP_THREADS, 6) void rope_minmax_kernel(
    const float* __restrict__ x,
    const float* __restrict__ cosb,
    const float* __restrict__ sinb,
    float* __restrict__ out,
    float* __restrict__ obs_max,
    float* __restrict__ obs_min)
{
    const unsigned FULL = 0xffffffffu;
    int wid  = threadIdx.x >> 5;
    int lane = threadIdx.x & 31;
    int hg   = blockIdx.x >> 10;                 // head group 0..7
    int tb   = blockIdx.x & (RP_TBLOCKS - 1);    // t-block within group
    int t    = tb * RP_TPB + wid;                // this warp's t
    int h0   = hg * RP_HPW;                      // first head

    // ---- DRAM-bound x loads first: 4 independent LDG.128.CS (4 heads, same t) ----
    float4 v[RP_HPW];
    #pragma unroll
    for (int j = 0; j < RP_HPW; j++) {
        size_t row = (size_t)(h0 + j) * RP_T + t;
        v[j] = __ldcs(reinterpret_cast<const float4*>(x + row * RP_D) + lane);
    }

    // ---- table loads once (default policy: reused across heads, L2-resident) ----
    float4 c = reinterpret_cast<const float4*>(cosb + (size_t)t * RP_D)[lane];
    float4 s = reinterpret_cast<const float4*>(sinb + (size_t)t * RP_D)[lane];

    float sign = (lane < 16) ? -1.0f : 1.0f;
    float4 sgs = make_float4(sign * s.x, sign * s.y, sign * s.z, sign * s.w);
    float mx[RP_HPW], mn[RP_HPW];

    #pragma unroll
    for (int j = 0; j < RP_HPW; j++) {
        // partner half (elements i +/- 64) lives in lane ^ 16
        float4 p;
        p.x = __shfl_xor_sync(FULL, v[j].x, 16);
        p.y = __shfl_xor_sync(FULL, v[j].y, 16);
        p.z = __shfl_xor_sync(FULL, v[j].z, 16);
        p.w = __shfl_xor_sync(FULL, v[j].w, 16);

        float4 o;
        o.x = fmaf(p.x, sgs.x, v[j].x * c.x);
        o.y = fmaf(p.y, sgs.y, v[j].y * c.y);
        o.z = fmaf(p.z, sgs.z, v[j].z * c.z);
        o.w = fmaf(p.w, sgs.w, v[j].w * c.w);

        size_t row = (size_t)(h0 + j) * RP_T + t;
        __stcs(reinterpret_cast<float4*>(out + row * RP_D) + lane, o);

        mx[j] = fmaxf(fmaxf(o.x, o.y), fmaxf(o.z, o.w));
        mn[j] = fminf(fminf(o.x, o.y), fminf(o.z, o.w));
    }

    // ---- 4 interleaved butterfly reductions ----
    #pragma unroll
    for (int off = 16; off > 0; off >>= 1) {
        #pragma unroll
        for (int j = 0; j < RP_HPW; j++) {
            mx[j] = fmaxf(mx[j], __shfl_xor_sync(FULL, mx[j], off));
            mn[j] = fminf(mn[j], __shfl_xor_sync(FULL, mn[j], off));
        }
    }

    // After butterfly every lane holds the result: lanes 0..3 store their row's stats.
    if (lane < RP_HPW) {
        size_t row = (size_t)(h0 + lane) * RP_T + t;
        obs_max[row] = mx[lane];
        obs_min[row] = mn[lane];
    }
}

extern "C" void kernel_launch(void* const* d_in, const int* in_sizes, int n_in,
                              void* d_out, int out_size) {
    // Input order: x, scale_x (unused), cos, scale_cos (unused), sin, scale_sin (unused)
    const float* x    = (const float*)d_in[0];
    const float* cosb = (const float*)d_in[2];
    const float* sinb = (const float*)d_in[4];

    float* out     = (float*)d_out;                    // H*T*D
    float* obs_max = out + (size_t)RP_ROWS * RP_D;     // H*T
    float* obs_min = obs_max + (size_t)RP_ROWS;        // H*T

    rope_minmax_kernel<<<RP_BLOCKS, RP_THREADS>>>(x, cosb, sinb, out, obs_max, obs_min);
}